// round 1
// baseline (speedup 1.0000x reference)
#include <cuda_runtime.h>
#include <cuda_bf16.h>
#include <math.h>

#define NHI 4096
#define NLO 262144
#define NT  (NHI + NLO)
#define EHI 65536
#define ELO 524288
#define ET  (EHI + ELO)
#define DIM 128
#define NHEAD 4
#define HDIM 32
#define SCALE 0.17677669529663687f   /* 1/sqrt(32) */

// ---------------- scratch (device globals; no allocation allowed) ----------------
__device__ float g_q[(size_t)NT * DIM];
__device__ float g_k[(size_t)NT * DIM];
__device__ float g_v[(size_t)NT * DIM];
__device__ float g_h[(size_t)NT * DIM];      // skip -> += agg -> LN+relu in place
__device__ unsigned g_mx[(size_t)NT * NHEAD];
__device__ float g_den[(size_t)NT * NHEAD];
__device__ float g_sc[(size_t)ET * NHEAD];
__device__ float g_pool[(size_t)NHI * DIM];
__device__ int   g_cnt[NHI];

// ---------------- helpers ----------------
__device__ __forceinline__ unsigned long long fma2(unsigned long long a,
                                                   unsigned long long b,
                                                   unsigned long long c) {
    unsigned long long d;
    asm("fma.rn.f32x2 %0, %1, %2, %3;" : "=l"(d) : "l"(a), "l"(b), "l"(c));
    return d;
}
__device__ __forceinline__ unsigned long long pack2(float x, float y) {
    unsigned long long d;
    asm("mov.b64 %0, {%1, %2};" : "=l"(d) : "f"(x), "f"(y));
    return d;
}
__device__ __forceinline__ void unpack2(unsigned long long v, float& x, float& y) {
    asm("mov.b64 {%0, %1}, %2;" : "=f"(x), "=f"(y) : "l"(v));
}
__device__ __forceinline__ unsigned fkey(float f) {
    unsigned u = __float_as_uint(f);
    return (u & 0x80000000u) ? ~u : (u | 0x80000000u);
}
__device__ __forceinline__ float finv(unsigned k) {
    unsigned u = (k & 0x80000000u) ? (k ^ 0x80000000u) : ~k;
    return __uint_as_float(u);
}
__device__ __forceinline__ float warp_sum(float v) {
    #pragma unroll
    for (int o = 16; o; o >>= 1) v += __shfl_xor_sync(0xffffffffu, v, o);
    return v;
}

// ---------------- K1: fused QKV+skip GEMM (f32x2 packed FMA) ----------------
__global__ void __launch_bounds__(256, 3)
gemm_qkvs(const float* __restrict__ xh, const float* __restrict__ xl,
          const float* __restrict__ Wq, const float* __restrict__ Wk,
          const float* __restrict__ Wv, const float* __restrict__ Ws,
          const float* __restrict__ bq, const float* __restrict__ bk,
          const float* __restrict__ bv, const float* __restrict__ bs)
{
    __shared__ float xs[64][128];   // 32 KB, broadcast reads -> no conflicts
    __shared__ float ws[32][128];   // 16 KB chunk of one weight matrix

    const int row0 = blockIdx.x * 64;
    const float* X = (row0 < NHI) ? (xh + (size_t)row0 * DIM)
                                  : (xl + (size_t)(row0 - NHI) * DIM);
    const int t = threadIdx.x;
    const int tx = t & 15;      // 16 column-groups of 8
    const int ty = t >> 4;      // 16 row-groups of 4

    #pragma unroll
    for (int i = 0; i < 32; i++) {
        int lin = t + 256 * i;          // 0..8191
        xs[lin >> 7][lin & 127] = X[lin];
    }

    const float* Wm[4] = {Wq, Wk, Wv, Ws};
    const float* Bm[4] = {bq, bk, bv, bs};
    float* Om[4] = {g_q, g_k, g_v, g_h};

    #pragma unroll
    for (int m = 0; m < 4; m++) {
        unsigned long long acc[4][4];
        #pragma unroll
        for (int r = 0; r < 4; r++)
            #pragma unroll
            for (int p = 0; p < 4; p++) acc[r][p] = 0ull;

        const float* W = Wm[m];
        for (int k0 = 0; k0 < 128; k0 += 32) {
            __syncthreads();
            #pragma unroll
            for (int i = 0; i < 16; i++) {
                int lin = t + 256 * i;  // 0..4095
                int kk = lin >> 7, c = lin & 127;
                ws[kk][c] = W[(size_t)(k0 + kk) * DIM + c];
            }
            __syncthreads();
            #pragma unroll
            for (int k = 0; k < 32; k++) {
                unsigned long long pa[4];
                #pragma unroll
                for (int r = 0; r < 4; r++) {
                    float a = xs[ty * 4 + r][k0 + k];
                    pa[r] = pack2(a, a);
                }
                ulonglong2 bA = *(const ulonglong2*)&ws[k][tx * 8];
                ulonglong2 bB = *(const ulonglong2*)&ws[k][tx * 8 + 4];
                #pragma unroll
                for (int r = 0; r < 4; r++) {
                    acc[r][0] = fma2(pa[r], bA.x, acc[r][0]);
                    acc[r][1] = fma2(pa[r], bA.y, acc[r][1]);
                    acc[r][2] = fma2(pa[r], bB.x, acc[r][2]);
                    acc[r][3] = fma2(pa[r], bB.y, acc[r][3]);
                }
            }
        }
        const float* B = Bm[m];
        float bias[8];
        #pragma unroll
        for (int j = 0; j < 8; j++) bias[j] = B[tx * 8 + j];
        float* O = Om[m] + (size_t)row0 * DIM + tx * 8;
        #pragma unroll
        for (int r = 0; r < 4; r++) {
            float o[8];
            #pragma unroll
            for (int p = 0; p < 4; p++) unpack2(acc[r][p], o[2 * p], o[2 * p + 1]);
            #pragma unroll
            for (int j = 0; j < 8; j++) o[j] += bias[j];
            float* dstp = O + (size_t)(ty * 4 + r) * DIM;
            *(float4*)dstp       = make_float4(o[0], o[1], o[2], o[3]);
            *(float4*)(dstp + 4) = make_float4(o[4], o[5], o[6], o[7]);
        }
    }
}

// ---------------- K2: per-edge scores + segment max ----------------
__global__ void edge_score(const int* __restrict__ ei, int E, int noff, int eoff)
{
    int e = blockIdx.x * 8 + threadIdx.y;
    if (e >= E) return;
    int lane = threadIdx.x;
    int src = ei[e] + noff;
    int dst = ei[E + e] + noff;
    const float* qr = g_q + (size_t)dst * DIM;
    const float* kr = g_k + (size_t)src * DIM;
    float s[NHEAD];
    #pragma unroll
    for (int h = 0; h < NHEAD; h++) {
        float p = qr[h * HDIM + lane] * kr[h * HDIM + lane];
        s[h] = warp_sum(p) * SCALE;
    }
    if (lane < NHEAD) {
        float sc = s[lane];
        g_sc[(size_t)(eoff + e) * NHEAD + lane] = sc;
        atomicMax(&g_mx[(size_t)dst * NHEAD + lane], fkey(sc));
    }
}

// ---------------- K3: exp(score - max) + denom ----------------
__global__ void edge_exp(const int* __restrict__ ei, int E, int noff, int eoff)
{
    int e = blockIdx.x * 256 + threadIdx.x;
    if (e >= E) return;
    int dst = ei[E + e] + noff;
    float4 sc = *(float4*)&g_sc[(size_t)(eoff + e) * NHEAD];
    const unsigned* mx = &g_mx[(size_t)dst * NHEAD];
    float* den = &g_den[(size_t)dst * NHEAD];
    float e0 = expf(sc.x - finv(mx[0]));
    float e1 = expf(sc.y - finv(mx[1]));
    float e2 = expf(sc.z - finv(mx[2]));
    float e3 = expf(sc.w - finv(mx[3]));
    atomicAdd(&den[0], e0);
    atomicAdd(&den[1], e1);
    atomicAdd(&den[2], e2);
    atomicAdd(&den[3], e3);
    *(float4*)&g_sc[(size_t)(eoff + e) * NHEAD] = make_float4(e0, e1, e2, e3);
}

// ---------------- K4: aggregate alpha * v into h (already holds skip) ----------------
__global__ void edge_agg(const int* __restrict__ ei, int E, int noff, int eoff)
{
    int e = blockIdx.x * 8 + threadIdx.y;
    if (e >= E) return;
    int lane = threadIdx.x;
    int src = ei[e] + noff;
    int dst = ei[E + e] + noff;
    const float* vr = g_v + (size_t)src * DIM;
    float* hr = g_h + (size_t)dst * DIM;
    #pragma unroll
    for (int h = 0; h < NHEAD; h++) {
        float alpha = g_sc[(size_t)(eoff + e) * NHEAD + h] /
                      g_den[(size_t)dst * NHEAD + h];
        atomicAdd(&hr[h * HDIM + lane], alpha * vr[h * HDIM + lane]);
    }
}

// ---------------- K5: LayerNorm + ReLU (in place), and pool low nodes ----------------
__global__ void ln_relu(const float* __restrict__ lnw, const float* __restrict__ lnb,
                        const int* __restrict__ batch)
{
    int node = blockIdx.x * 8 + threadIdx.y;
    int lane = threadIdx.x;
    float* row = g_h + (size_t)node * DIM;
    float4 v = ((float4*)row)[lane];
    float s = warp_sum(v.x + v.y + v.z + v.w);
    float sq = warp_sum(v.x * v.x + v.y * v.y + v.z * v.z + v.w * v.w);
    float mean = s * (1.0f / 128.0f);
    float var = sq * (1.0f / 128.0f) - mean * mean;
    float rstd = rsqrtf(var + 1e-5f);
    float4 w = ((const float4*)lnw)[lane];
    float4 b = ((const float4*)lnb)[lane];
    float4 o;
    o.x = fmaxf((v.x - mean) * rstd * w.x + b.x, 0.0f);
    o.y = fmaxf((v.y - mean) * rstd * w.y + b.y, 0.0f);
    o.z = fmaxf((v.z - mean) * rstd * w.z + b.z, 0.0f);
    o.w = fmaxf((v.w - mean) * rstd * w.w + b.w, 0.0f);
    ((float4*)row)[lane] = o;
    if (node >= NHI) {
        int g = batch[node - NHI];
        float* p = g_pool + (size_t)g * DIM + lane * 4;
        atomicAdd(p + 0, o.x);
        atomicAdd(p + 1, o.y);
        atomicAdd(p + 2, o.z);
        atomicAdd(p + 3, o.w);
        if (lane == 0) atomicAdd(&g_cnt[g], 1);
    }
}

// ---------------- K6: high-node gating epilogue ----------------
__global__ void final_high(const float* __restrict__ wlh, float* __restrict__ out)
{
    int i = blockIdx.x * 8 + threadIdx.y;
    int lane = threadIdx.x;
    const float* hrow = g_h + (size_t)i * DIM;
    float4 hv = ((const float4*)hrow)[lane];
    float cnt = fmaxf((float)g_cnt[i], 1.0f);
    float inv = 1.0f / cnt;
    float4 pv = ((const float4*)(g_pool + (size_t)i * DIM))[lane];
    pv.x *= inv; pv.y *= inv; pv.z *= inv; pv.w *= inv;
    float4 w0 = ((const float4*)wlh)[lane];
    float4 w1 = ((const float4*)(wlh + DIM))[lane];
    float d = hv.x * w0.x + hv.y * w0.y + hv.z * w0.z + hv.w * w0.w
            + pv.x * w1.x + pv.y * w1.y + pv.z * w1.z + pv.w * w1.w;
    d = warp_sum(d);
    float sgm = 1.0f / (1.0f + expf(-d));
    float4 o;
    o.x = sgm * hv.x + (1.0f - sgm) * pv.x;
    o.y = sgm * hv.y + (1.0f - sgm) * pv.y;
    o.z = sgm * hv.z + (1.0f - sgm) * pv.z;
    o.w = sgm * hv.w + (1.0f - sgm) * pv.w;
    ((float4*)(out + (size_t)i * DIM))[lane] = o;
}

// ---------------- K7: low-node gating epilogue ----------------
__global__ void final_low(const float* __restrict__ whl, const int* __restrict__ batch,
                          float* __restrict__ out)
{
    int j = blockIdx.x * 8 + threadIdx.y;
    int lane = threadIdx.x;
    int g = batch[j];
    float4 hb = ((const float4*)(g_h + (size_t)g * DIM))[lane];
    float4 lv = ((const float4*)(g_h + (size_t)(NHI + j) * DIM))[lane];
    float4 w0 = ((const float4*)whl)[lane];
    float4 w1 = ((const float4*)(whl + DIM))[lane];
    float d = hb.x * w0.x + hb.y * w0.y + hb.z * w0.z + hb.w * w0.w
            + lv.x * w1.x + lv.y * w1.y + lv.z * w1.z + lv.w * w1.w;
    d = warp_sum(d);
    float a = 1.0f / (1.0f + expf(-d));
    float4 o;
    o.x = a * lv.x + (1.0f - a) * hb.x;
    o.y = a * lv.y + (1.0f - a) * hb.y;
    o.z = a * lv.z + (1.0f - a) * hb.z;
    o.w = a * lv.w + (1.0f - a) * hb.w;
    ((float4*)(out + (size_t)j * DIM))[lane] = o;
}

// ---------------- launch ----------------
extern "C" void kernel_launch(void* const* d_in, const int* in_sizes, int n_in,
                              void* d_out, int out_size)
{
    const float* high_emb = (const float*)d_in[0];
    const float* low_emb  = (const float*)d_in[1];
    const float* Wq = (const float*)d_in[2];  const float* bq = (const float*)d_in[3];
    const float* Wk = (const float*)d_in[4];  const float* bk = (const float*)d_in[5];
    const float* Wv = (const float*)d_in[6];  const float* bv = (const float*)d_in[7];
    const float* Ws = (const float*)d_in[8];  const float* bs = (const float*)d_in[9];
    const float* lnw = (const float*)d_in[10];
    const float* lnb = (const float*)d_in[11];
    const float* wlh = (const float*)d_in[12];
    const float* whl = (const float*)d_in[13];
    const int* eih   = (const int*)d_in[14];
    const int* eil   = (const int*)d_in[15];
    const int* batch = (const int*)d_in[16];
    float* out = (float*)d_out;

    void *pmx, *pden, *ppool, *pcnt;
    cudaGetSymbolAddress(&pmx, g_mx);
    cudaGetSymbolAddress(&pden, g_den);
    cudaGetSymbolAddress(&ppool, g_pool);
    cudaGetSymbolAddress(&pcnt, g_cnt);
    cudaMemsetAsync(pmx, 0, (size_t)NT * NHEAD * sizeof(unsigned), 0);
    cudaMemsetAsync(pden, 0, (size_t)NT * NHEAD * sizeof(float), 0);
    cudaMemsetAsync(ppool, 0, (size_t)NHI * DIM * sizeof(float), 0);
    cudaMemsetAsync(pcnt, 0, NHI * sizeof(int), 0);

    gemm_qkvs<<<NT / 64, 256>>>(high_emb, low_emb, Wq, Wk, Wv, Ws, bq, bk, bv, bs);

    dim3 t32x8(32, 8);
    edge_score<<<EHI / 8, t32x8>>>(eih, EHI, 0, 0);
    edge_score<<<ELO / 8, t32x8>>>(eil, ELO, NHI, EHI);
    edge_exp<<<EHI / 256, 256>>>(eih, EHI, 0, 0);
    edge_exp<<<ELO / 256, 256>>>(eil, ELO, NHI, EHI);
    edge_agg<<<EHI / 8, t32x8>>>(eih, EHI, 0, 0);
    edge_agg<<<ELO / 8, t32x8>>>(eil, ELO, NHI, EHI);

    ln_relu<<<NT / 8, t32x8>>>(lnw, lnb, batch);
    final_high<<<NHI / 8, t32x8>>>(wlh, out);
    final_low<<<NLO / 8, t32x8>>>(whl, batch, out + (size_t)NHI * DIM);
}

// round 3
// speedup vs baseline: 1.7744x; 1.7744x over previous
#include <cuda_runtime.h>
#include <cuda_bf16.h>
#include <mma.h>
#include <math.h>
#include <cstdint>

using namespace nvcuda;

#define NHI 4096
#define NLO 262144
#define NT  (NHI + NLO)
#define EHI 65536
#define ELO 524288
#define ET  (EHI + ELO)
#define DIM 128
#define NHEAD 4
#define HDIM 32
#define SCALE 0.17677669529663687f   /* 1/sqrt(32) */

// ---------------- scratch (device globals; no allocation allowed) ----------------
__device__ float g_q[(size_t)NT * DIM];
__device__ float g_k[(size_t)NT * DIM];
__device__ float g_v[(size_t)NT * DIM];
__device__ float g_h[(size_t)NT * DIM];      // skip -> += agg -> LN+relu in place
__device__ unsigned g_mx[(size_t)NT * NHEAD];
__device__ float g_den[(size_t)NT * NHEAD];
__device__ float g_sc[(size_t)ET * NHEAD];
__device__ float g_pool[(size_t)NHI * DIM];
__device__ int   g_cnt[NHI];
// W^T bf16 hi/lo images: [matrix 0..3][n 0..127][k 0..127]
__device__ __align__(16) __nv_bfloat16 g_wt_hi[4 * 128 * 128];
__device__ __align__(16) __nv_bfloat16 g_wt_lo[4 * 128 * 128];
// bias broadcast tiles: [matrix][16 rows][128 cols] (all rows identical)
__device__ __align__(16) float g_btile[4 * 16 * 128];

// ---------------- helpers ----------------
__device__ __forceinline__ unsigned fkey(float f) {
    unsigned u = __float_as_uint(f);
    return (u & 0x80000000u) ? ~u : (u | 0x80000000u);
}
__device__ __forceinline__ float finv(unsigned k) {
    unsigned u = (k & 0x80000000u) ? (k ^ 0x80000000u) : ~k;
    return __uint_as_float(u);
}
__device__ __forceinline__ float warp_sum(float v) {
    #pragma unroll
    for (int o = 16; o; o >>= 1) v += __shfl_xor_sync(0xffffffffu, v, o);
    return v;
}

// ---------------- K0a: prep weights -> W^T bf16 hi/lo ----------------
__global__ void prep_w(const float* __restrict__ Wq, const float* __restrict__ Wk,
                       const float* __restrict__ Wv, const float* __restrict__ Ws)
{
    int idx = blockIdx.x * 256 + threadIdx.x;  // 0..65535
    int m = idx >> 14;       // matrix 0..3
    int n = (idx >> 7) & 127;
    int k = idx & 127;
    const float* W = (m == 0) ? Wq : (m == 1) ? Wk : (m == 2) ? Wv : Ws;
    float w = W[k * 128 + n];
    __nv_bfloat16 hi = __float2bfloat16(w);
    __nv_bfloat16 lo = __float2bfloat16(w - __bfloat162float(hi));
    g_wt_hi[idx] = hi;
    g_wt_lo[idx] = lo;
}

// ---------------- K0b: prep bias tiles ----------------
__global__ void prep_b(const float* __restrict__ bq, const float* __restrict__ bk,
                       const float* __restrict__ bv, const float* __restrict__ bs)
{
    int idx = blockIdx.x * 256 + threadIdx.x;  // 0..8191
    int m = idx >> 11;
    int n = idx & 127;
    const float* B = (m == 0) ? bq : (m == 1) ? bk : (m == 2) ? bv : bs;
    g_btile[idx] = B[n];
}

// ---------------- K1: fused QKV+skip GEMM via HMMA (bf16x3 split) ----------------
// SMEM (bf16 elems): A_hi[128][136], A_lo[128][136], B_hi[128][136], B_lo[128][136]
#define LDA 136
#define SM_ALO (128 * LDA)
#define SM_BHI (2 * 128 * LDA)
#define SM_BLO (3 * 128 * LDA)
#define SM_BYTES (4 * 128 * LDA * 2)

__global__ void __launch_bounds__(256, 1)
gemm_hmma(const float* __restrict__ xh, const float* __restrict__ xl)
{
    extern __shared__ __nv_bfloat16 sm[];
    const int t = threadIdx.x;
    const int wid = t >> 5;
    const int wm = wid & 3;        // warp row group: 32 rows each
    const int wn = wid >> 2;       // warp col group: 64 cols each

    // ---- load + split-convert A tile (128 rows x 128 k) ----
    const int row0 = blockIdx.x * 128;
    const float* X = (row0 < NHI) ? (xh + (size_t)row0 * DIM)
                                  : (xl + (size_t)(row0 - NHI) * DIM);
    #pragma unroll
    for (int j = 0; j < 16; j++) {
        int v = t + 256 * j;            // float4 index 0..4095
        int r = v >> 5;                 // row 0..127
        int k0 = (v & 31) * 4;          // k 0..124
        float4 x = ((const float4*)X)[v];
        float xs[4] = {x.x, x.y, x.z, x.w};
        unsigned short h[4], l[4];
        #pragma unroll
        for (int i = 0; i < 4; i++) {
            __nv_bfloat16 bh = __float2bfloat16(xs[i]);
            __nv_bfloat16 bl = __float2bfloat16(xs[i] - __bfloat162float(bh));
            h[i] = *(unsigned short*)&bh;
            l[i] = *(unsigned short*)&bl;
        }
        uint2 hv = make_uint2((uint32_t)h[0] | ((uint32_t)h[1] << 16),
                              (uint32_t)h[2] | ((uint32_t)h[3] << 16));
        uint2 lv = make_uint2((uint32_t)l[0] | ((uint32_t)l[1] << 16),
                              (uint32_t)l[2] | ((uint32_t)l[3] << 16));
        *(uint2*)(sm + r * LDA + k0)          = hv;
        *(uint2*)(sm + SM_ALO + r * LDA + k0) = lv;
    }

    float* Om[4] = {g_q, g_k, g_v, g_h};

    #pragma unroll
    for (int m = 0; m < 4; m++) {
        __syncthreads();   // previous epilogue done before overwriting B smem
        // copy W^T hi/lo (L2-resident) into padded smem
        const uint4* ghi = (const uint4*)(g_wt_hi + m * 128 * 128);
        const uint4* glo = (const uint4*)(g_wt_lo + m * 128 * 128);
        #pragma unroll
        for (int j = 0; j < 8; j++) {
            int idx = t + 256 * j;      // 0..2047 (uint4 = 8 bf16)
            int n = idx >> 4;
            int c = idx & 15;
            *(uint4*)(sm + SM_BHI + n * LDA + c * 8) = ghi[idx];
            *(uint4*)(sm + SM_BLO + n * LDA + c * 8) = glo[idx];
        }
        __syncthreads();

        // accumulators: 2 (m) x 4 (n) tiles of 16x16, init from bias tile
        wmma::fragment<wmma::accumulator, 16, 16, 16, float> acc[2][4];
        #pragma unroll
        for (int i = 0; i < 2; i++)
            #pragma unroll
            for (int j = 0; j < 4; j++)
                wmma::load_matrix_sync(acc[i][j],
                    g_btile + m * 16 * 128 + wn * 64 + j * 16, 128,
                    wmma::mem_row_major);

        #pragma unroll
        for (int ks = 0; ks < 8; ks++) {
            wmma::fragment<wmma::matrix_a, 16, 16, 16, __nv_bfloat16, wmma::row_major> ah[2], al[2];
            wmma::fragment<wmma::matrix_b, 16, 16, 16, __nv_bfloat16, wmma::col_major> bh[4], bl[4];
            #pragma unroll
            for (int i = 0; i < 2; i++) {
                int r = wm * 32 + i * 16;
                wmma::load_matrix_sync(ah[i], sm + r * LDA + ks * 16, LDA);
                wmma::load_matrix_sync(al[i], sm + SM_ALO + r * LDA + ks * 16, LDA);
            }
            #pragma unroll
            for (int j = 0; j < 4; j++) {
                int n = wn * 64 + j * 16;
                wmma::load_matrix_sync(bh[j], sm + SM_BHI + n * LDA + ks * 16, LDA);
                wmma::load_matrix_sync(bl[j], sm + SM_BLO + n * LDA + ks * 16, LDA);
            }
            #pragma unroll
            for (int i = 0; i < 2; i++)
                #pragma unroll
                for (int j = 0; j < 4; j++) {
                    wmma::mma_sync(acc[i][j], ah[i], bh[j], acc[i][j]);
                    wmma::mma_sync(acc[i][j], al[i], bh[j], acc[i][j]);
                    wmma::mma_sync(acc[i][j], ah[i], bl[j], acc[i][j]);
                }
        }

        // store
        float* O = Om[m] + (size_t)row0 * DIM;
        #pragma unroll
        for (int i = 0; i < 2; i++)
            #pragma unroll
            for (int j = 0; j < 4; j++)
                wmma::store_matrix_sync(
                    O + (size_t)(wm * 32 + i * 16) * DIM + wn * 64 + j * 16,
                    acc[i][j], DIM, wmma::mem_row_major);
    }
}

// ---------------- K2: per-edge scores + segment max ----------------
__global__ void edge_score(const int* __restrict__ ei, int E, int noff, int eoff)
{
    int e = blockIdx.x * 8 + threadIdx.y;
    if (e >= E) return;
    int lane = threadIdx.x;
    int src = ei[e] + noff;
    int dst = ei[E + e] + noff;
    const float* qr = g_q + (size_t)dst * DIM;
    const float* kr = g_k + (size_t)src * DIM;
    float s[NHEAD];
    #pragma unroll
    for (int h = 0; h < NHEAD; h++) {
        float p = qr[h * HDIM + lane] * kr[h * HDIM + lane];
        s[h] = warp_sum(p) * SCALE;
    }
    if (lane < NHEAD) {
        float sc = s[lane];
        g_sc[(size_t)(eoff + e) * NHEAD + lane] = sc;
        atomicMax(&g_mx[(size_t)dst * NHEAD + lane], fkey(sc));
    }
}

// ---------------- K3: exp(score - max) + denom ----------------
__global__ void edge_exp(const int* __restrict__ ei, int E, int noff, int eoff)
{
    int e = blockIdx.x * 256 + threadIdx.x;
    if (e >= E) return;
    int dst = ei[E + e] + noff;
    float4 sc = *(float4*)&g_sc[(size_t)(eoff + e) * NHEAD];
    const unsigned* mx = &g_mx[(size_t)dst * NHEAD];
    float* den = &g_den[(size_t)dst * NHEAD];
    float e0 = expf(sc.x - finv(mx[0]));
    float e1 = expf(sc.y - finv(mx[1]));
    float e2 = expf(sc.z - finv(mx[2]));
    float e3 = expf(sc.w - finv(mx[3]));
    atomicAdd(&den[0], e0);
    atomicAdd(&den[1], e1);
    atomicAdd(&den[2], e2);
    atomicAdd(&den[3], e3);
    *(float4*)&g_sc[(size_t)(eoff + e) * NHEAD] = make_float4(e0, e1, e2, e3);
}

// ---------------- K4: aggregate alpha * v into h (already holds skip) ----------------
__global__ void edge_agg(const int* __restrict__ ei, int E, int noff, int eoff)
{
    int e = blockIdx.x * 8 + threadIdx.y;
    if (e >= E) return;
    int lane = threadIdx.x;
    int src = ei[e] + noff;
    int dst = ei[E + e] + noff;
    const float* vr = g_v + (size_t)src * DIM;
    float* hr = g_h + (size_t)dst * DIM;
    #pragma unroll
    for (int h = 0; h < NHEAD; h++) {
        float alpha = g_sc[(size_t)(eoff + e) * NHEAD + h] /
                      g_den[(size_t)dst * NHEAD + h];
        atomicAdd(&hr[h * HDIM + lane], alpha * vr[h * HDIM + lane]);
    }
}

// ---------------- K5: LayerNorm + ReLU (in place), and pool low nodes ----------------
__global__ void ln_relu(const float* __restrict__ lnw, const float* __restrict__ lnb,
                        const int* __restrict__ batch)
{
    int node = blockIdx.x * 8 + threadIdx.y;
    int lane = threadIdx.x;
    float* row = g_h + (size_t)node * DIM;
    float4 v = ((float4*)row)[lane];
    float s = warp_sum(v.x + v.y + v.z + v.w);
    float sq = warp_sum(v.x * v.x + v.y * v.y + v.z * v.z + v.w * v.w);
    float mean = s * (1.0f / 128.0f);
    float var = sq * (1.0f / 128.0f) - mean * mean;
    float rstd = rsqrtf(var + 1e-5f);
    float4 w = ((const float4*)lnw)[lane];
    float4 b = ((const float4*)lnb)[lane];
    float4 o;
    o.x = fmaxf((v.x - mean) * rstd * w.x + b.x, 0.0f);
    o.y = fmaxf((v.y - mean) * rstd * w.y + b.y, 0.0f);
    o.z = fmaxf((v.z - mean) * rstd * w.z + b.z, 0.0f);
    o.w = fmaxf((v.w - mean) * rstd * w.w + b.w, 0.0f);
    ((float4*)row)[lane] = o;
    if (node >= NHI) {
        int g = batch[node - NHI];
        float* p = g_pool + (size_t)g * DIM + lane * 4;
        atomicAdd(p + 0, o.x);
        atomicAdd(p + 1, o.y);
        atomicAdd(p + 2, o.z);
        atomicAdd(p + 3, o.w);
        if (lane == 0) atomicAdd(&g_cnt[g], 1);
    }
}

// ---------------- K6: high-node gating epilogue ----------------
__global__ void final_high(const float* __restrict__ wlh, float* __restrict__ out)
{
    int i = blockIdx.x * 8 + threadIdx.y;
    int lane = threadIdx.x;
    const float* hrow = g_h + (size_t)i * DIM;
    float4 hv = ((const float4*)hrow)[lane];
    float cnt = fmaxf((float)g_cnt[i], 1.0f);
    float inv = 1.0f / cnt;
    float4 pv = ((const float4*)(g_pool + (size_t)i * DIM))[lane];
    pv.x *= inv; pv.y *= inv; pv.z *= inv; pv.w *= inv;
    float4 w0 = ((const float4*)wlh)[lane];
    float4 w1 = ((const float4*)(wlh + DIM))[lane];
    float d = hv.x * w0.x + hv.y * w0.y + hv.z * w0.z + hv.w * w0.w
            + pv.x * w1.x + pv.y * w1.y + pv.z * w1.z + pv.w * w1.w;
    d = warp_sum(d);
    float sgm = 1.0f / (1.0f + expf(-d));
    float4 o;
    o.x = sgm * hv.x + (1.0f - sgm) * pv.x;
    o.y = sgm * hv.y + (1.0f - sgm) * pv.y;
    o.z = sgm * hv.z + (1.0f - sgm) * pv.z;
    o.w = sgm * hv.w + (1.0f - sgm) * pv.w;
    ((float4*)(out + (size_t)i * DIM))[lane] = o;
}

// ---------------- K7: low-node gating epilogue ----------------
__global__ void final_low(const float* __restrict__ whl, const int* __restrict__ batch,
                          float* __restrict__ out)
{
    int j = blockIdx.x * 8 + threadIdx.y;
    int lane = threadIdx.x;
    int g = batch[j];
    float4 hb = ((const float4*)(g_h + (size_t)g * DIM))[lane];
    float4 lv = ((const float4*)(g_h + (size_t)(NHI + j) * DIM))[lane];
    float4 w0 = ((const float4*)whl)[lane];
    float4 w1 = ((const float4*)(whl + DIM))[lane];
    float d = hb.x * w0.x + hb.y * w0.y + hb.z * w0.z + hb.w * w0.w
            + lv.x * w1.x + lv.y * w1.y + lv.z * w1.z + lv.w * w1.w;
    d = warp_sum(d);
    float a = 1.0f / (1.0f + expf(-d));
    float4 o;
    o.x = a * lv.x + (1.0f - a) * hb.x;
    o.y = a * lv.y + (1.0f - a) * hb.y;
    o.z = a * lv.z + (1.0f - a) * hb.z;
    o.w = a * lv.w + (1.0f - a) * hb.w;
    ((float4*)(out + (size_t)j * DIM))[lane] = o;
}

// ---------------- launch ----------------
extern "C" void kernel_launch(void* const* d_in, const int* in_sizes, int n_in,
                              void* d_out, int out_size)
{
    const float* high_emb = (const float*)d_in[0];
    const float* low_emb  = (const float*)d_in[1];
    const float* Wq = (const float*)d_in[2];  const float* bq = (const float*)d_in[3];
    const float* Wk = (const float*)d_in[4];  const float* bk = (const float*)d_in[5];
    const float* Wv = (const float*)d_in[6];  const float* bv = (const float*)d_in[7];
    const float* Ws = (const float*)d_in[8];  const float* bs = (const float*)d_in[9];
    const float* lnw = (const float*)d_in[10];
    const float* lnb = (const float*)d_in[11];
    const float* wlh = (const float*)d_in[12];
    const float* whl = (const float*)d_in[13];
    const int* eih   = (const int*)d_in[14];
    const int* eil   = (const int*)d_in[15];
    const int* batch = (const int*)d_in[16];
    float* out = (float*)d_out;

    void *pmx, *pden, *ppool, *pcnt;
    cudaGetSymbolAddress(&pmx, g_mx);
    cudaGetSymbolAddress(&pden, g_den);
    cudaGetSymbolAddress(&ppool, g_pool);
    cudaGetSymbolAddress(&pcnt, g_cnt);
    cudaMemsetAsync(pmx, 0, (size_t)NT * NHEAD * sizeof(unsigned), 0);
    cudaMemsetAsync(pden, 0, (size_t)NT * NHEAD * sizeof(float), 0);
    cudaMemsetAsync(ppool, 0, (size_t)NHI * DIM * sizeof(float), 0);
    cudaMemsetAsync(pcnt, 0, NHI * sizeof(int), 0);

    cudaFuncSetAttribute(gemm_hmma, cudaFuncAttributeMaxDynamicSharedMemorySize, SM_BYTES);

    prep_w<<<256, 256>>>(Wq, Wk, Wv, Ws);
    prep_b<<<32, 256>>>(bq, bk, bv, bs);
    gemm_hmma<<<NT / 128, 256, SM_BYTES>>>(high_emb, low_emb);

    dim3 t32x8(32, 8);
    edge_score<<<EHI / 8, t32x8>>>(eih, EHI, 0, 0);
    edge_score<<<ELO / 8, t32x8>>>(eil, ELO, NHI, EHI);
    edge_exp<<<EHI / 256, 256>>>(eih, EHI, 0, 0);
    edge_exp<<<ELO / 256, 256>>>(eil, ELO, NHI, EHI);
    edge_agg<<<EHI / 8, t32x8>>>(eih, EHI, 0, 0);
    edge_agg<<<ELO / 8, t32x8>>>(eil, ELO, NHI, EHI);

    ln_relu<<<NT / 8, t32x8>>>(lnw, lnb, batch);
    final_high<<<NHI / 8, t32x8>>>(wlh, out);
    final_low<<<NLO / 8, t32x8>>>(whl, batch, out + (size_t)NHI * DIM);
}